// round 10
// baseline (speedup 1.0000x reference)
#include <cuda_runtime.h>

// NSLayer: out = x + (w0*A + ... + w6*A^7 + w7*I) @ x,  A = I - x x^T
// Gram-space: A^k x = x B^k, B = I - x^T x (symmetric 8x8).
//   out = x * P,  P = c0 I + c1 B + ... + c7 B^7, c0 = 1+w7, ck = w_{k-1}
// Paterson-Stockmeyer (Z = B^2):
//   P = ((D3 Z + D2) Z + D1) Z + D0,  Di = c_{2i} I + c_{2i+1} B
//   -> 4 symmetric products instead of 6.
// All operands are commuting polynomials of B -> products symmetric, and we
// can put Z (smem) as the i,k-multiplier: acc[j] += Z[i][k]*T[k][j]
// (1 LDS.64 per 8 FFMA2). B and Z live in smem; only the T ping-pong stays
// in registers -> ~160 regs -> 3 CTAs/SM (12 warps).

typedef unsigned long long ull;

#define NMAT (2048 * 128)
#define THREADS 128
#define MATS_PER_CTA 256                  // 2 per thread (f32x2 lane packing)
#define SLAB 73                           // ull per thread (odd mod 16)
#define SMEM_BYTES (THREADS * SLAB * 8)   // 74752 B
#define Z_OFF 36                          // Z triangle offset in slab (ull)

__device__ __forceinline__ int tri(int i, int j) {  // i <= j
    return i * 8 - (i * (i + 1)) / 2 + j;
}
__device__ __forceinline__ int trix(int i, int j) { // either order
    return (i <= j) ? tri(i, j) : tri(j, i);
}
__device__ __forceinline__ ull sg2(const ull* T, int i, int j) {
    return T[trix(i, j)];
}

__device__ __forceinline__ ull pack2(float lo, float hi) {
    ull r; asm("mov.b64 %0,{%1,%2};" : "=l"(r) : "f"(lo), "f"(hi)); return r;
}
__device__ __forceinline__ ull fma2(ull a, ull b, ull c) {
    ull d; asm("fma.rn.f32x2 %0,%1,%2,%3;" : "=l"(d) : "l"(a), "l"(b), "l"(c)); return d;
}
__device__ __forceinline__ ull mul2(ull a, ull b) {
    ull d; asm("mul.rn.f32x2 %0,%1,%2;" : "=l"(d) : "l"(a), "l"(b)); return d;
}
__device__ __forceinline__ ull add2(ull a, ull b) {
    ull d; asm("add.rn.f32x2 %0,%1,%2;" : "=l"(d) : "l"(a), "l"(b)); return d;
}
__device__ __forceinline__ float ldw(const float* p) {
    float v; asm volatile("ld.global.nc.f32 %0,[%1];" : "=f"(v) : "l"(p)); return v;
}
// volatile global load (defeats CSE with staged copy)
__device__ __forceinline__ float4 ldg4v(const float4* p) {
    float4 v;
    asm volatile("ld.global.nc.v4.f32 {%0,%1,%2,%3}, [%4];"
                 : "=f"(v.x), "=f"(v.y), "=f"(v.z), "=f"(v.w) : "l"(p));
    return v;
}

// dst = Z * src + (a I + b B);  Z, B in smem (slab), src/dst in regs.
// Z[i][k] is the j-loop-invariant smem operand.
__device__ __forceinline__ void ps_step(ull* __restrict__ dst,
                                        const ull* __restrict__ slab,  // B at 0, Z at Z_OFF
                                        const ull* __restrict__ src,
                                        ull a2, ull b2) {
#pragma unroll
    for (int i = 0; i < 8; ++i) {
        ull acc[8];
        {
            ull z0 = slab[Z_OFF + trix(i, 0)];
#pragma unroll
            for (int j = i; j < 8; ++j) acc[j] = mul2(z0, sg2(src, 0, j));
        }
#pragma unroll
        for (int k = 1; k < 8; ++k) {
            ull zk = slab[Z_OFF + trix(i, k)];
#pragma unroll
            for (int j = i; j < 8; ++j) acc[j] = fma2(zk, sg2(src, k, j), acc[j]);
        }
#pragma unroll
        for (int j = i; j < 8; ++j) {
            ull v = fma2(b2, slab[trix(i, j)], acc[j]);   // + b*B
            dst[tri(i, j)] = (i == j) ? add2(v, a2) : v;  // + a*I on diag
        }
    }
}

__global__ __launch_bounds__(THREADS, 3) void nslayer_kernel(
    const float* __restrict__ x_g,
    const float* __restrict__ w_g,
    float* __restrict__ out_g)
{
    extern __shared__ float sf[];
    const int tid = threadIdx.x;

    // ---- stage x: coalesced global -> interleaved-pair smem ----
    // pair p = matrices (2p, 2p+1); float offset of (mat m, elem e):
    //   (m>>1)*(2*SLAB) + 2*e + (m&1)
    const float4* gx = reinterpret_cast<const float4*>(x_g)
                     + (size_t)blockIdx.x * (MATS_PER_CTA * 16);
#pragma unroll
    for (int it = 0; it < 32; ++it) {
        int idx = it * THREADS + tid;
        float4 v = gx[idx];
        int gf = idx << 2;
        int m = gf >> 6, e = gf & 63;
        float* s = sf + (m >> 1) * (2 * SLAB) + 2 * e + (m & 1);
        s[0] = v.x; s[2] = v.y; s[4] = v.z; s[6] = v.w;
    }
    __syncthreads();

    ull* my = reinterpret_cast<ull*>(sf) + tid * SLAB;

    // ---- Gram: B = I - x^T x  (packed triangle, regs) ----
    ull B2[36];
    {
#pragma unroll
        for (int k = 0; k < 8; ++k) {
            ull xr[8];
#pragma unroll
            for (int c = 0; c < 8; ++c) xr[c] = my[k * 8 + c];
#pragma unroll
            for (int i = 0; i < 8; ++i) {
                ull xi = xr[i];
#pragma unroll
                for (int j = i; j < 8; ++j) {
                    if (k == 0) B2[tri(i, j)] = mul2(xi, xr[j]);
                    else        B2[tri(i, j)] = fma2(xi, xr[j], B2[tri(i, j)]);
                }
            }
        }
        const ull m1 = pack2(-1.0f, -1.0f);
        const ull one2 = pack2(1.0f, 1.0f);
#pragma unroll
        for (int i = 0; i < 8; ++i)
#pragma unroll
            for (int j = i; j < 8; ++j)
                B2[tri(i, j)] = fma2(B2[tri(i, j)], m1, (i == j) ? one2 : 0ull);
    }
    // B -> smem slab [0..35]  (overwrites x[0..17]; x regs-free, x dead after Z)
    // NOTE: x[36..63] still needed? No: Gram is done, Z below uses B regs only;
    // final x*P rereads x from global. Safe to overwrite the whole slab.
#pragma unroll
    for (int t = 0; t < 36; ++t) my[t] = B2[t];

    // ---- Z = B*B -> smem slab [36..71]  (B still in regs) ----
#pragma unroll
    for (int i = 0; i < 8; ++i) {
        ull acc[8];
        {
            ull b0 = sg2(B2, i, 0);
#pragma unroll
            for (int j = i; j < 8; ++j) acc[j] = mul2(b0, sg2(B2, 0, j));
        }
#pragma unroll
        for (int k = 1; k < 8; ++k) {
            ull bk = sg2(B2, i, k);
#pragma unroll
            for (int j = i; j < 8; ++j) acc[j] = fma2(bk, sg2(B2, k, j), acc[j]);
        }
#pragma unroll
        for (int j = i; j < 8; ++j) my[Z_OFF + tri(i, j)] = acc[j];
    }

    // ---- T0 = D3 = w5 I + w6 B  (from B regs; B regs die here) ----
    ull T0[36], T1[36];
    {
        float w6 = ldw(w_g + 6), w5 = ldw(w_g + 5);
        ull w6_2 = pack2(w6, w6), w5_2 = pack2(w5, w5);
#pragma unroll
        for (int i = 0; i < 8; ++i)
#pragma unroll
            for (int j = i; j < 8; ++j) {
                ull v = mul2(B2[tri(i, j)], w6_2);
                T0[tri(i, j)] = (i == j) ? add2(v, w5_2) : v;
            }
    }

    // ---- Paterson-Stockmeyer Horner in Z ----
    { float a = ldw(w_g + 3), b = ldw(w_g + 4);
      ps_step(T1, my, T0, pack2(a, a), pack2(b, b)); }
    { float a = ldw(w_g + 1), b = ldw(w_g + 2);
      ps_step(T0, my, T1, pack2(a, a), pack2(b, b)); }
    { float a = 1.0f + ldw(w_g + 7), b = ldw(w_g + 0);
      ps_step(T1, my, T0, pack2(a, a), pack2(b, b)); }
    // T1 = P (symmetric, packed)

    // ---- out = x * P : x rereads from global (L2-warm), rows -> slab ----
    const float4* xa = reinterpret_cast<const float4*>(x_g)
                     + ((size_t)blockIdx.x * MATS_PER_CTA + 2 * tid) * 16;
#pragma unroll
    for (int i = 0; i < 8; ++i) {
        float4 a0 = ldg4v(xa + 2 * i);          // mat a, row i, cols 0-3
        float4 a1 = ldg4v(xa + 2 * i + 1);      // mat a, row i, cols 4-7
        float4 b0 = ldg4v(xa + 16 + 2 * i);     // mat b, row i
        float4 b1 = ldg4v(xa + 16 + 2 * i + 1);
        ull xr[8] = { pack2(a0.x, b0.x), pack2(a0.y, b0.y),
                      pack2(a0.z, b0.z), pack2(a0.w, b0.w),
                      pack2(a1.x, b1.x), pack2(a1.y, b1.y),
                      pack2(a1.z, b1.z), pack2(a1.w, b1.w) };
        ull acc[8];
        {
            ull x0 = xr[0];
#pragma unroll
            for (int j = 0; j < 8; ++j) acc[j] = mul2(x0, sg2(T1, 0, j));
        }
#pragma unroll
        for (int k = 1; k < 8; ++k) {
            ull xk = xr[k];
#pragma unroll
            for (int j = 0; j < 8; ++j) acc[j] = fma2(xk, sg2(T1, k, j), acc[j]);
        }
#pragma unroll
        for (int j = 0; j < 8; ++j) my[i * 8 + j] = acc[j];
    }
    __syncthreads();

    // ---- coalesced smem -> global store ----
    float4* go = reinterpret_cast<float4*>(out_g)
               + (size_t)blockIdx.x * (MATS_PER_CTA * 16);
#pragma unroll
    for (int it = 0; it < 32; ++it) {
        int idx = it * THREADS + tid;
        int gf = idx << 2;
        int m = gf >> 6, e = gf & 63;
        const float* s = sf + (m >> 1) * (2 * SLAB) + 2 * e + (m & 1);
        float4 v;
        v.x = s[0]; v.y = s[2]; v.z = s[4]; v.w = s[6];
        go[idx] = v;
    }
}

extern "C" void kernel_launch(void* const* d_in, const int* in_sizes, int n_in,
                              void* d_out, int out_size) {
    const float* x_g = (const float*)d_in[0];   // (2048,128,8,8) fp32
    const float* w_g = (const float*)d_in[1];   // 14 fp32 (w[0..7] used)
    float* out_g = (float*)d_out;

    cudaFuncSetAttribute(nslayer_kernel,
                         cudaFuncAttributeMaxDynamicSharedMemorySize, SMEM_BYTES);

    const int blocks = NMAT / MATS_PER_CTA;     // 1024
    nslayer_kernel<<<blocks, THREADS, SMEM_BYTES>>>(x_g, w_g, out_g);
}

// round 11
// speedup vs baseline: 1.2708x; 1.2708x over previous
#include <cuda_runtime.h>

// NSLayer: out = x + (w0*A + ... + w6*A^7 + w7*I) @ x,  A = I - x x^T
// Gram-space: A^k x = x B^k, B = I - x^T x (symmetric 8x8).
//   out = x * P,  P = (1+w7) I + sum w_{k-1} B^k   (triangle Horner)
//
// f32x2 packing: 2 matrices/thread, every fp op is fma.rn.f32x2.
// Occupancy fix (R10 bug: both Horner temps in regs -> spill):
//   - B stays in REGISTERS (72) = the dense j-varying operand
//   - Horner temp T ping-pongs between two SMEM triangle slots;
//     T[i][k] is j-invariant -> 1 LDS.64 per 8 FFMA2
//   - final P loaded back into B's dead registers for all-reg x*P
// -> ~140-150 live regs -> 3 CTAs x 128 thr = 12 warps/SM.

typedef unsigned long long ull;

#define NMAT (2048 * 128)
#define THREADS 128
#define MATS_PER_CTA 256                  // 2 per thread
#define SLAB 73                           // ull per thread
#define SMEM_BYTES (THREADS * SLAB * 8)   // 74752 B -> 3 CTAs/SM
#define TA 0                              // Horner slot A (ull offset in slab)
#define TB 36                             // Horner slot B

__device__ __forceinline__ int tri(int i, int j) {  // i <= j
    return i * 8 - (i * (i + 1)) / 2 + j;
}
__device__ __forceinline__ int trix(int i, int j) { // either order
    return (i <= j) ? tri(i, j) : tri(j, i);
}
__device__ __forceinline__ ull sg2(const ull* T, int i, int j) {
    return T[trix(i, j)];
}

__device__ __forceinline__ ull pack2(float lo, float hi) {
    ull r; asm("mov.b64 %0,{%1,%2};" : "=l"(r) : "f"(lo), "f"(hi)); return r;
}
__device__ __forceinline__ ull fma2(ull a, ull b, ull c) {
    ull d; asm("fma.rn.f32x2 %0,%1,%2,%3;" : "=l"(d) : "l"(a), "l"(b), "l"(c)); return d;
}
__device__ __forceinline__ ull mul2(ull a, ull b) {
    ull d; asm("mul.rn.f32x2 %0,%1,%2;" : "=l"(d) : "l"(a), "l"(b)); return d;
}
__device__ __forceinline__ ull add2(ull a, ull b) {
    ull d; asm("add.rn.f32x2 %0,%1,%2;" : "=l"(d) : "l"(a), "l"(b)); return d;
}
__device__ __forceinline__ float ldw(const float* p) {
    float v; asm volatile("ld.global.nc.f32 %0,[%1];" : "=f"(v) : "l"(p)); return v;
}
__device__ __forceinline__ float4 ldg4v(const float4* p) {
    float4 v;
    asm volatile("ld.global.nc.v4.f32 {%0,%1,%2,%3}, [%4];"
                 : "=f"(v.x), "=f"(v.y), "=f"(v.z), "=f"(v.w) : "l"(p));
    return v;
}

// smem T (src slot) x reg B -> smem dst slot:  dst = T*B + wt*I
// T[i][k] is j-loop-invariant (1 LDS.64 per 8 fma2); B[k][j] from regs.
__device__ __forceinline__ void step_sm(ull* __restrict__ my, int dstOff, int srcOff,
                                        const ull* __restrict__ B2, ull wt2) {
#pragma unroll
    for (int i = 0; i < 8; ++i) {
        ull acc[8];
        {
            ull t0 = my[srcOff + trix(i, 0)];
#pragma unroll
            for (int j = i; j < 8; ++j) acc[j] = mul2(t0, sg2(B2, 0, j));
        }
#pragma unroll
        for (int k = 1; k < 8; ++k) {
            ull tk = my[srcOff + trix(i, k)];
#pragma unroll
            for (int j = i; j < 8; ++j) acc[j] = fma2(tk, sg2(B2, k, j), acc[j]);
        }
#pragma unroll
        for (int j = i; j < 8; ++j)
            my[dstOff + tri(i, j)] = (i == j) ? add2(acc[j], wt2) : acc[j];
    }
}

__global__ __launch_bounds__(THREADS, 3) void nslayer_kernel(
    const float* __restrict__ x_g,
    const float* __restrict__ w_g,
    float* __restrict__ out_g)
{
    extern __shared__ float sf[];
    const int tid = threadIdx.x;

    // ---- stage x: coalesced global -> interleaved-pair smem ----
    // pair p = matrices (2p, 2p+1); float offset of (mat m, elem e):
    //   (m>>1)*(2*SLAB) + 2*e + (m&1)
    const float4* gx = reinterpret_cast<const float4*>(x_g)
                     + (size_t)blockIdx.x * (MATS_PER_CTA * 16);
#pragma unroll
    for (int it = 0; it < 32; ++it) {
        int idx = it * THREADS + tid;
        float4 v = gx[idx];
        int gf = idx << 2;
        int m = gf >> 6, e = gf & 63;
        float* s = sf + (m >> 1) * (2 * SLAB) + 2 * e + (m & 1);
        s[0] = v.x; s[2] = v.y; s[4] = v.z; s[6] = v.w;
    }
    __syncthreads();

    ull* my = reinterpret_cast<ull*>(sf) + tid * SLAB;

    // ---- Gram: B = I - x^T x  (packed triangle, REGISTERS) ----
    ull B2[36];
    {
#pragma unroll
        for (int k = 0; k < 8; ++k) {
            ull xr[8];
#pragma unroll
            for (int c = 0; c < 8; ++c) xr[c] = my[k * 8 + c];
#pragma unroll
            for (int i = 0; i < 8; ++i) {
                ull xi = xr[i];
#pragma unroll
                for (int j = i; j < 8; ++j) {
                    if (k == 0) B2[tri(i, j)] = mul2(xi, xr[j]);
                    else        B2[tri(i, j)] = fma2(xi, xr[j], B2[tri(i, j)]);
                }
            }
        }
        const ull m1 = pack2(-1.0f, -1.0f);
        const ull one2 = pack2(1.0f, 1.0f);
#pragma unroll
        for (int i = 0; i < 8; ++i)
#pragma unroll
            for (int j = i; j < 8; ++j)
                B2[tri(i, j)] = fma2(B2[tri(i, j)], m1, (i == j) ? one2 : 0ull);
    }
    // x in slab is DEAD now (final x*P rereads global) -> reuse slab for T.

    // ---- init T(slot A) = w6 B + w5 I ----
    {
        float w6 = ldw(w_g + 6), w5 = ldw(w_g + 5);
        ull w6_2 = pack2(w6, w6), w5_2 = pack2(w5, w5);
#pragma unroll
        for (int i = 0; i < 8; ++i)
#pragma unroll
            for (int j = i; j < 8; ++j) {
                ull v = mul2(B2[tri(i, j)], w6_2);
                my[TA + tri(i, j)] = (i == j) ? add2(v, w5_2) : v;
            }
    }

    // ---- Horner: T <- w_t I + T*B   (T in smem ping-pong, B in regs) ----
    { float w = ldw(w_g + 4); step_sm(my, TB, TA, B2, pack2(w, w)); }
    { float w = ldw(w_g + 3); step_sm(my, TA, TB, B2, pack2(w, w)); }
    { float w = ldw(w_g + 2); step_sm(my, TB, TA, B2, pack2(w, w)); }
    { float w = ldw(w_g + 1); step_sm(my, TA, TB, B2, pack2(w, w)); }
    { float w = ldw(w_g + 0); step_sm(my, TB, TA, B2, pack2(w, w)); }
    { float w = 1.0f + ldw(w_g + 7); step_sm(my, TA, TB, B2, pack2(w, w)); }
    // P = slot A (symmetric, packed)

    // ---- P -> registers (B2 is dead; compiler reuses its regs) ----
    ull P2[36];
#pragma unroll
    for (int t = 0; t < 36; ++t) P2[t] = my[TA + t];

    // ---- out = x * P : x reread from global (L2-warm), all-register ----
    const float4* xa = reinterpret_cast<const float4*>(x_g)
                     + ((size_t)blockIdx.x * MATS_PER_CTA + 2 * tid) * 16;
#pragma unroll
    for (int i = 0; i < 8; ++i) {
        float4 a0 = ldg4v(xa + 2 * i);          // mat a row i cols 0-3
        float4 a1 = ldg4v(xa + 2 * i + 1);
        float4 b0 = ldg4v(xa + 16 + 2 * i);     // mat b row i
        float4 b1 = ldg4v(xa + 16 + 2 * i + 1);
        ull xr[8] = { pack2(a0.x, b0.x), pack2(a0.y, b0.y),
                      pack2(a0.z, b0.z), pack2(a0.w, b0.w),
                      pack2(a1.x, b1.x), pack2(a1.y, b1.y),
                      pack2(a1.z, b1.z), pack2(a1.w, b1.w) };
        ull acc[8];
        {
            ull x0 = xr[0];
#pragma unroll
            for (int j = 0; j < 8; ++j) acc[j] = mul2(x0, sg2(P2, 0, j));
        }
#pragma unroll
        for (int k = 1; k < 8; ++k) {
            ull xk = xr[k];
#pragma unroll
            for (int j = 0; j < 8; ++j) acc[j] = fma2(xk, sg2(P2, k, j), acc[j]);
        }
#pragma unroll
        for (int j = 0; j < 8; ++j) my[i * 8 + j] = acc[j];
    }
    __syncthreads();

    // ---- coalesced smem -> global store ----
    float4* go = reinterpret_cast<float4*>(out_g)
               + (size_t)blockIdx.x * (MATS_PER_CTA * 16);
#pragma unroll
    for (int it = 0; it < 32; ++it) {
        int idx = it * THREADS + tid;
        int gf = idx << 2;
        int m = gf >> 6, e = gf & 63;
        const float* s = sf + (m >> 1) * (2 * SLAB) + 2 * e + (m & 1);
        float4 v;
        v.x = s[0]; v.y = s[2]; v.z = s[4]; v.w = s[6];
        go[idx] = v;
    }
}

extern "C" void kernel_launch(void* const* d_in, const int* in_sizes, int n_in,
                              void* d_out, int out_size) {
    const float* x_g = (const float*)d_in[0];   // (2048,128,8,8) fp32
    const float* w_g = (const float*)d_in[1];   // 14 fp32 (w[0..7] used)
    float* out_g = (float*)d_out;

    cudaFuncSetAttribute(nslayer_kernel,
                         cudaFuncAttributeMaxDynamicSharedMemorySize, SMEM_BYTES);

    const int blocks = NMAT / MATS_PER_CTA;     // 1024
    nslayer_kernel<<<blocks, THREADS, SMEM_BYTES>>>(x_g, w_g, out_g);
}

// round 13
// speedup vs baseline: 1.3745x; 1.0817x over previous
#include <cuda_runtime.h>

// NSLayer: out = x + (w0*A + ... + w6*A^7 + w7*I) @ x,  A = I - x x^T
// Gram-space: A^k x = x B^k, B = I - x^T x (symmetric 8x8).
//   out = x * P,  P = (1+w7) I + sum w_{k-1} B^k   (triangle Horner)
//
// Placement (R11 fix): B -> smem (read-only, i-invariant multiplier,
// 1 LDS.64 per up-to-8 FFMA2); BOTH Horner temps (src T, dst acc) in
// registers (dense j-varying operands). ~156 live regs -> 3 CTAs/SM,
// 12 warps. f32x2 packing: 2 matrices/thread.

typedef unsigned long long ull;

#define NMAT (2048 * 128)
#define THREADS 128
#define MATS_PER_CTA 256                  // 2 per thread
#define SLAB 65                           // ull per thread; 65 mod 16 = 1 -> LDS.64 conflict-free
#define SMEM_BYTES (THREADS * SLAB * 8)   // 66560 B -> 3 CTAs/SM (199.7 KB)

__device__ __forceinline__ int tri(int i, int j) {  // i <= j
    return i * 8 - (i * (i + 1)) / 2 + j;
}
__device__ __forceinline__ int trix(int i, int j) { // either order
    return (i <= j) ? tri(i, j) : tri(j, i);
}
__device__ __forceinline__ ull sg2(const ull* T, int i, int j) {
    return T[trix(i, j)];
}

__device__ __forceinline__ ull pack2(float lo, float hi) {
    ull r; asm("mov.b64 %0,{%1,%2};" : "=l"(r) : "f"(lo), "f"(hi)); return r;
}
__device__ __forceinline__ ull fma2(ull a, ull b, ull c) {
    ull d; asm("fma.rn.f32x2 %0,%1,%2,%3;" : "=l"(d) : "l"(a), "l"(b), "l"(c)); return d;
}
__device__ __forceinline__ ull mul2(ull a, ull b) {
    ull d; asm("mul.rn.f32x2 %0,%1,%2;" : "=l"(d) : "l"(a), "l"(b)); return d;
}
__device__ __forceinline__ ull add2(ull a, ull b) {
    ull d; asm("add.rn.f32x2 %0,%1,%2;" : "=l"(d) : "l"(a), "l"(b)); return d;
}
__device__ __forceinline__ float ldw(const float* p) {
    float v; asm volatile("ld.global.nc.f32 %0,[%1];" : "=f"(v) : "l"(p)); return v;
}
__device__ __forceinline__ float4 ldg4v(const float4* p) {
    float4 v;
    asm volatile("ld.global.nc.v4.f32 {%0,%1,%2,%3}, [%4];"
                 : "=f"(v.x), "=f"(v.y), "=f"(v.z), "=f"(v.w) : "l"(p));
    return v;
}

// dst = src * B + wt * I.   src/dst: register triangles. B: smem triangle.
// Loop (k,j) outer, i inner: B[k][j] loaded once, reused across i<=j.
__device__ __forceinline__ void step_rr(ull* __restrict__ dst,
                                        const ull* __restrict__ src,
                                        const ull* __restrict__ myB,  // smem
                                        ull wt2) {
#pragma unroll
    for (int k = 0; k < 8; ++k) {
#pragma unroll
        for (int j = 0; j < 8; ++j) {
            ull b = myB[trix(k, j)];           // 1 LDS.64, reused over i
#pragma unroll
            for (int i = 0; i <= j; ++i) {
                ull t = sg2(src, i, k);
                if (k == 0) dst[tri(i, j)] = mul2(t, b);
                else        dst[tri(i, j)] = fma2(t, b, dst[tri(i, j)]);
            }
        }
    }
#pragma unroll
    for (int d = 0; d < 8; ++d)
        dst[tri(d, d)] = add2(dst[tri(d, d)], wt2);
}

__global__ __launch_bounds__(THREADS, 3) void nslayer_kernel(
    const float* __restrict__ x_g,
    const float* __restrict__ w_g,
    float* __restrict__ out_g)
{
    extern __shared__ float sf[];
    const int tid = threadIdx.x;

    // ---- stage x: coalesced global -> interleaved-pair smem ----
    // pair p = matrices (2p, 2p+1); float offset of (mat m, elem e):
    //   (m>>1)*(2*SLAB) + 2*e + (m&1)
    const float4* gx = reinterpret_cast<const float4*>(x_g)
                     + (size_t)blockIdx.x * (MATS_PER_CTA * 16);
#pragma unroll
    for (int it = 0; it < 32; ++it) {
        int idx = it * THREADS + tid;
        float4 v = gx[idx];
        int gf = idx << 2;
        int m = gf >> 6, e = gf & 63;
        float* s = sf + (m >> 1) * (2 * SLAB) + 2 * e + (m & 1);
        s[0] = v.x; s[2] = v.y; s[4] = v.z; s[6] = v.w;
    }
    __syncthreads();

    ull* my = reinterpret_cast<ull*>(sf) + tid * SLAB;

    // ---- Gram: B = I - x^T x  (packed triangle, regs) ----
    ull TA[36];                      // will hold B transiently, then Horner temp
    {
#pragma unroll
        for (int k = 0; k < 8; ++k) {
            ull xr[8];
#pragma unroll
            for (int c = 0; c < 8; ++c) xr[c] = my[k * 8 + c];
#pragma unroll
            for (int i = 0; i < 8; ++i) {
                ull xi = xr[i];
#pragma unroll
                for (int j = i; j < 8; ++j) {
                    if (k == 0) TA[tri(i, j)] = mul2(xi, xr[j]);
                    else        TA[tri(i, j)] = fma2(xi, xr[j], TA[tri(i, j)]);
                }
            }
        }
        const ull m1 = pack2(-1.0f, -1.0f);
        const ull one2 = pack2(1.0f, 1.0f);
#pragma unroll
        for (int i = 0; i < 8; ++i)
#pragma unroll
            for (int j = i; j < 8; ++j)
                TA[tri(i, j)] = fma2(TA[tri(i, j)], m1, (i == j) ? one2 : 0ull);
    }

    // x in slab is dead (final x*P rereads global). B -> smem slab [0..35].
#pragma unroll
    for (int t = 0; t < 36; ++t) my[t] = TA[t];

    // ---- T(A) = w6 B + w5 I   (in place over B's registers) ----
    {
        float w6 = ldw(w_g + 6), w5 = ldw(w_g + 5);
        ull w6_2 = pack2(w6, w6), w5_2 = pack2(w5, w5);
#pragma unroll
        for (int i = 0; i < 8; ++i)
#pragma unroll
            for (int j = i; j < 8; ++j) {
                ull v = mul2(TA[tri(i, j)], w6_2);
                TA[tri(i, j)] = (i == j) ? add2(v, w5_2) : v;
            }
    }

    // ---- Horner: T <- w_t I + T*B   (T reg ping-pong, B smem) ----
    ull TB[36];
    { float w = ldw(w_g + 4); step_rr(TB, TA, my, pack2(w, w)); }
    { float w = ldw(w_g + 3); step_rr(TA, TB, my, pack2(w, w)); }
    { float w = ldw(w_g + 2); step_rr(TB, TA, my, pack2(w, w)); }
    { float w = ldw(w_g + 1); step_rr(TA, TB, my, pack2(w, w)); }
    { float w = ldw(w_g + 0); step_rr(TB, TA, my, pack2(w, w)); }
    { float w = 1.0f + ldw(w_g + 7); step_rr(TA, TB, my, pack2(w, w)); }
    // P = TA (symmetric, packed, registers)

    // ---- out = x * P : x reread from global (L2-warm); rows -> slab ----
    const float4* xa = reinterpret_cast<const float4*>(x_g)
                     + ((size_t)blockIdx.x * MATS_PER_CTA + 2 * tid) * 16;
#pragma unroll
    for (int i = 0; i < 8; ++i) {
        float4 a0 = ldg4v(xa + 2 * i);          // mat a row i cols 0-3
        float4 a1 = ldg4v(xa + 2 * i + 1);
        float4 b0 = ldg4v(xa + 16 + 2 * i);     // mat b row i
        float4 b1 = ldg4v(xa + 16 + 2 * i + 1);
        ull xr[8] = { pack2(a0.x, b0.x), pack2(a0.y, b0.y),
                      pack2(a0.z, b0.z), pack2(a0.w, b0.w),
                      pack2(a1.x, b1.x), pack2(a1.y, b1.y),
                      pack2(a1.z, b1.z), pack2(a1.w, b1.w) };
        ull acc[8];
        {
            ull x0 = xr[0];
#pragma unroll
            for (int j = 0; j < 8; ++j) acc[j] = mul2(x0, sg2(TA, 0, j));
        }
#pragma unroll
        for (int k = 1; k < 8; ++k) {
            ull xk = xr[k];
#pragma unroll
            for (int j = 0; j < 8; ++j) acc[j] = fma2(xk, sg2(TA, k, j), acc[j]);
        }
#pragma unroll
        for (int j = 0; j < 8; ++j) my[i * 8 + j] = acc[j];  // clobbers B: dead
    }
    __syncthreads();

    // ---- coalesced smem -> global store ----
    float4* go = reinterpret_cast<float4*>(out_g)
               + (size_t)blockIdx.x * (MATS_PER_CTA * 16);
#pragma unroll
    for (int it = 0; it < 32; ++it) {
        int idx = it * THREADS + tid;
        int gf = idx << 2;
        int m = gf >> 6, e = gf & 63;
        const float* s = sf + (m >> 1) * (2 * SLAB) + 2 * e + (m & 1);
        float4 v;
        v.x = s[0]; v.y = s[2]; v.z = s[4]; v.w = s[6];
        go[idx] = v;
    }
}

extern "C" void kernel_launch(void* const* d_in, const int* in_sizes, int n_in,
                              void* d_out, int out_size) {
    const float* x_g = (const float*)d_in[0];   // (2048,128,8,8) fp32
    const float* w_g = (const float*)d_in[1];   // 14 fp32 (w[0..7] used)
    float* out_g = (float*)d_out;

    cudaFuncSetAttribute(nslayer_kernel,
                         cudaFuncAttributeMaxDynamicSharedMemorySize, SMEM_BYTES);

    const int blocks = NMAT / MATS_PER_CTA;     // 1024
    nslayer_kernel<<<blocks, THREADS, SMEM_BYTES>>>(x_g, w_g, out_g);
}

// round 14
// speedup vs baseline: 1.9590x; 1.4252x over previous
#include <cuda_runtime.h>

// NSLayer: out = x + (w0*A + ... + w6*A^7 + w7*I) @ x,  A = I - x x^T
// Gram-space: A^k x = x B^k, B = I - x^T x (symmetric 8x8).
//   out = x * P,  P = (1+w7) I + sum w_{k-1} B^k   (triangle Horner)
//
// SCALAR, occupancy-first (R13 lesson: packed f32x2 working set can't fit
// a 3-CTA reg cap; f32x2 also measured far below 2x MAC rate):
//   - 1 matrix/thread, 128 thr x 4 CTAs/SM = 16 warps/SM (cap 128 regs)
//   - Horner temps T0/T1 (36+36 floats) in REGISTERS
//   - B in SMEM slab (read once per (k,j), reused over i<=j)
//   - slab stride 101 floats: gcd(101,32)=1 -> all scalar LDS conflict-free
//   - x staged in slab, final x*P reads/writes slab in place (no reread)
//   - coalesced float4 staging in/out

#define NMAT (2048 * 128)
#define THREADS 128
#define SLAB_F 101                          // floats per thread slab
#define B_OFF 64                            // B triangle at slab[64..99]
#define SMEM_BYTES (THREADS * SLAB_F * 4)   // 51712 B -> 4 CTAs/SM

__device__ __forceinline__ int tri(int i, int j) {  // i <= j
    return i * 8 - (i * (i + 1)) / 2 + j;
}
__device__ __forceinline__ int trix(int i, int j) {
    return (i <= j) ? tri(i, j) : tri(j, i);
}

__device__ __forceinline__ float ldw(const float* p) {
    float v; asm volatile("ld.global.nc.f32 %0,[%1];" : "=f"(v) : "l"(p)); return v;
}

// dst = src * B + wt * I.  src/dst: reg triangles. B: per-thread smem triangle.
// (k,j) outer, i inner: B value loaded once, reused over i<=j (reg multiplier).
__device__ __forceinline__ void step_sB(float* __restrict__ dst,
                                        const float* __restrict__ src,
                                        const float* __restrict__ myB, float wt) {
#pragma unroll
    for (int k = 0; k < 8; ++k) {
#pragma unroll
        for (int j = 0; j < 8; ++j) {
            float b = myB[trix(k, j)];
#pragma unroll
            for (int i = 0; i <= j; ++i) {
                float t = src[trix(i, k)];
                if (k == 0) dst[tri(i, j)] = t * b;
                else        dst[tri(i, j)] = fmaf(t, b, dst[tri(i, j)]);
            }
        }
    }
#pragma unroll
    for (int d = 0; d < 8; ++d) dst[tri(d, d)] += wt;
}

__global__ __launch_bounds__(THREADS, 4) void nslayer_kernel(
    const float* __restrict__ x_g,
    const float* __restrict__ w_g,
    float* __restrict__ out_g)
{
    extern __shared__ float sf[];
    const int tid = threadIdx.x;

    // ---- stage x: coalesced LDG.128 -> per-matrix slabs ----
    // CTA covers 128 matrices (= 2048 float4). thread does 16 float4.
    const float4* gx = reinterpret_cast<const float4*>(x_g)
                     + (size_t)blockIdx.x * (THREADS * 16);
#pragma unroll
    for (int it = 0; it < 16; ++it) {
        int idx = it * THREADS + tid;
        float4 v = gx[idx];
        int gf = idx << 2;
        int m = gf >> 6, e = gf & 63;
        float* s = sf + m * SLAB_F + e;
        s[0] = v.x; s[1] = v.y; s[2] = v.z; s[3] = v.w;
    }
    __syncthreads();

    float* my = sf + tid * SLAB_F;

    // ---- Gram: B = I - x^T x  (triangle, regs) ----
    float B[36];
    {
#pragma unroll
        for (int k = 0; k < 8; ++k) {
            float xr[8];
#pragma unroll
            for (int c = 0; c < 8; ++c) xr[c] = my[k * 8 + c];
#pragma unroll
            for (int i = 0; i < 8; ++i) {
                float xi = xr[i];
#pragma unroll
                for (int j = i; j < 8; ++j) {
                    if (k == 0) B[tri(i, j)] = xi * xr[j];
                    else        B[tri(i, j)] = fmaf(xi, xr[j], B[tri(i, j)]);
                }
            }
        }
#pragma unroll
        for (int i = 0; i < 8; ++i)
#pragma unroll
            for (int j = i; j < 8; ++j)
                B[tri(i, j)] = (i == j ? 1.0f : 0.0f) - B[tri(i, j)];
    }

    // B -> smem slab [64..99]
#pragma unroll
    for (int t = 0; t < 36; ++t) my[B_OFF + t] = B[t];

    // ---- T0 = w6 B + w5 I  (reuses B's registers) ----
    float T0[36], T1[36];
    {
        float w6 = ldw(w_g + 6), w5 = ldw(w_g + 5);
#pragma unroll
        for (int i = 0; i < 8; ++i)
#pragma unroll
            for (int j = i; j < 8; ++j)
                T0[tri(i, j)] = w6 * B[tri(i, j)] + (i == j ? w5 : 0.0f);
    }

    // ---- Horner: T <- w_t I + T*B  (T reg ping-pong, B from smem) ----
    { float w = ldw(w_g + 4); step_sB(T1, T0, my + B_OFF, w); }
    { float w = ldw(w_g + 3); step_sB(T0, T1, my + B_OFF, w); }
    { float w = ldw(w_g + 2); step_sB(T1, T0, my + B_OFF, w); }
    { float w = ldw(w_g + 1); step_sB(T0, T1, my + B_OFF, w); }
    { float w = ldw(w_g + 0); step_sB(T1, T0, my + B_OFF, w); }
    { float w = 1.0f + ldw(w_g + 7); step_sB(T0, T1, my + B_OFF, w); }
    // P = T0 (symmetric triangle, registers)

    // ---- out = x * P : x rows from own slab, write back in place ----
#pragma unroll
    for (int i = 0; i < 8; ++i) {
        float xr[8];
#pragma unroll
        for (int c = 0; c < 8; ++c) xr[c] = my[i * 8 + c];
        float acc[8];
        {
            float x0 = xr[0];
#pragma unroll
            for (int j = 0; j < 8; ++j) acc[j] = x0 * T0[trix(0, j)];
        }
#pragma unroll
        for (int k = 1; k < 8; ++k) {
            float xk = xr[k];
#pragma unroll
            for (int j = 0; j < 8; ++j) acc[j] = fmaf(xk, T0[trix(k, j)], acc[j]);
        }
#pragma unroll
        for (int j = 0; j < 8; ++j) my[i * 8 + j] = acc[j];
    }
    __syncthreads();

    // ---- coalesced slab -> global store ----
    float4* go = reinterpret_cast<float4*>(out_g)
               + (size_t)blockIdx.x * (THREADS * 16);
#pragma unroll
    for (int it = 0; it < 16; ++it) {
        int idx = it * THREADS + tid;
        int gf = idx << 2;
        int m = gf >> 6, e = gf & 63;
        const float* s = sf + m * SLAB_F + e;
        float4 v;
        v.x = s[0]; v.y = s[1]; v.z = s[2]; v.w = s[3];
        go[idx] = v;
    }
}

extern "C" void kernel_launch(void* const* d_in, const int* in_sizes, int n_in,
                              void* d_out, int out_size) {
    const float* x_g = (const float*)d_in[0];   // (2048,128,8,8) fp32
    const float* w_g = (const float*)d_in[1];   // 14 fp32 (w[0..7] used)
    float* out_g = (float*)d_out;

    cudaFuncSetAttribute(nslayer_kernel,
                         cudaFuncAttributeMaxDynamicSharedMemorySize, SMEM_BYTES);

    const int blocks = NMAT / THREADS;          // 2048
    nslayer_kernel<<<blocks, THREADS, SMEM_BYTES>>>(x_g, w_g, out_g);
}